// round 17
// baseline (speedup 1.0000x reference)
#include <cuda_runtime.h>
#include <cuda_fp16.h>
#include <cstdint>

// LCA layer via mma.sync (HMMA), factored + precision-budgeted:
//   b = x@W~ ; u1 = 0.1 b ; 9x { t = a@W~^T ; u += 0.1(b - (tW~ - a*diag) - u) }
//   out = a@W~^T      (W~ = fp16(W); all GEMMs 1-term fp16, fp32 accum)
// R17: u state stored fp16 (decayed-random-walk error ~5.5e-4); epilogue
//      traffic of the big kernels drops 12 -> 8 B/element.

#define MDIM   8192
#define DMODEL 1024
#define DLCA   4096
#define LAMV   0.1f
#define RATEV  0.1f

// ---- 1-term 128x128 geometry: KC=64, 128B rows, SW128 c^(r&7) ----
#define KC1    64
#define ROWB1  128
#define T1_B   (128 * ROWB1)         // 16384
#define STAGE1 (2 * T1_B)            // 32768
#define SMEM1  (3 * STAGE1)          // 98304

// ---- 1-term 64x128 geometry: KC=64, 3 CTAs/SM ----
#define TE_A   (64 * ROWB1)          // 8192
#define TE_B   (128 * ROWB1)         // 16384
#define STAGEE (TE_A + TE_B)         // 24576
#define SMEME  (3 * STAGEE)          // 73728

// state (all fp16)
__device__ __align__(16) __half g_bh[(size_t)MDIM * DLCA];
__device__ __align__(16) __half g_uh[(size_t)MDIM * DLCA];
__device__ float g_diag[DLCA];
// fp16 operands
__device__ __align__(16) __half g_ahi[(size_t)MDIM * DLCA];
__device__ __align__(16) __half g_thi[(size_t)MDIM * DMODEL];
__device__ __align__(16) __half g_xhi[(size_t)MDIM * DMODEL];
__device__ __align__(16) __half g_Whi[(size_t)DMODEL * DLCA];
__device__ __align__(16) __half g_Wthi[(size_t)DLCA * DMODEL];

__device__ __forceinline__ uint32_t smem_u32(const void* p) {
    uint32_t a;
    asm("{ .reg .u64 t; cvta.to.shared.u64 t, %1; cvt.u32.u64 %0, t; }" : "=r"(a) : "l"(p));
    return a;
}
__device__ __forceinline__ void ldsm4(uint32_t r[4], uint32_t addr) {
    asm volatile("ldmatrix.sync.aligned.m8n8.x4.shared.b16 {%0,%1,%2,%3}, [%4];"
                 : "=r"(r[0]), "=r"(r[1]), "=r"(r[2]), "=r"(r[3]) : "r"(addr));
}
__device__ __forceinline__ void mma16816(float c[4], const uint32_t a[4], const uint32_t b[2]) {
    asm volatile("mma.sync.aligned.m16n8k16.row.col.f32.f16.f16.f32 "
                 "{%0,%1,%2,%3}, {%4,%5,%6,%7}, {%8,%9}, {%0,%1,%2,%3};"
                 : "+f"(c[0]), "+f"(c[1]), "+f"(c[2]), "+f"(c[3])
                 : "r"(a[0]), "r"(a[1]), "r"(a[2]), "r"(a[3]), "r"(b[0]), "r"(b[1]));
}
#define CP_ASYNC(dst, src) \
    asm volatile("cp.async.cg.shared.global [%0], [%1], 16;" :: "r"(dst), "l"(src) : "memory")
#define CP_COMMIT() asm volatile("cp.async.commit_group;" ::: "memory")
#define CP_WAIT1()  asm volatile("cp.async.wait_group 1;" ::: "memory")

// ---------------- prep kernels ----------------
__global__ void split_x_kernel(const float* __restrict__ x) {
    size_t i = (size_t)blockIdx.x * blockDim.x + threadIdx.x;
    g_xhi[i] = __float2half_rn(x[i]);
}
__global__ void splitW_kernel(const float* __restrict__ W) {
    __shared__ float tile[32][33];
    int n0 = blockIdx.x * 32, k0 = blockIdx.y * 32;
    int tx = threadIdx.x, ty = threadIdx.y;
    #pragma unroll
    for (int r = 0; r < 4; r++) {
        int k = k0 + ty + r * 8;
        float v = W[(size_t)k * DLCA + n0 + tx];
        g_Whi[(size_t)k * DLCA + n0 + tx] = __float2half_rn(v);
        tile[ty + r * 8][tx] = v;
    }
    __syncthreads();
    #pragma unroll
    for (int r = 0; r < 4; r++) {
        int n = n0 + ty + r * 8;
        float v = tile[tx][ty + r * 8];
        g_Wthi[(size_t)n * DMODEL + k0 + tx] = __float2half_rn(v);
    }
}
__global__ void diag_kernel(const float* __restrict__ W) {
    int j = blockIdx.x * blockDim.x + threadIdx.x;
    float s = 0.0f;
    #pragma unroll 8
    for (int k = 0; k < DMODEL; k++) {
        float w = W[(size_t)k * DLCA + j];
        s = fmaf(w, w, s);
    }
    g_diag[j] = s;
}

// ========== 128x128 1-term GEMM (KC=64, 3-stage, 256thr, 64x32 warp) ==========
// EPI 0 (binit): A=xhi, B=Wthi -> bh, uh=0.1v, ahi
// EPI 3 (upd):   A=thi, B=Wthi -> u update; ahi
template <int EPI>
__global__ __launch_bounds__(256, 2)
void lca_gemm_big()
{
    constexpr int Kdim = DMODEL;
    constexpr int Nout = DLCA;
    constexpr int NC   = Kdim / KC1;

    const __half* Ahp = (EPI == 0) ? g_xhi : g_thi;

    extern __shared__ __align__(16) char smem[];
    const uint32_t sbase = smem_u32(smem);

    const int tid = threadIdx.x;
    const int wid = tid >> 5, l = tid & 31;
    const int wm = wid >> 2, wn = wid & 3;
    const int mBase = blockIdx.y * 128;
    const int nBase = blockIdx.x * 128;

    const __half* Ah = Ahp + (size_t)mBase * Kdim;
    const __half* Bh = g_Wthi + (size_t)nBase * Kdim;

    auto load_stage = [&](int s, int k0) {
        uint32_t sb = sbase + s * STAGE1;
        #pragma unroll
        for (int i = 0; i < 4; i++) {
            int u = tid + i * 256;
            int r = u >> 3, cc = u & 7;
            uint32_t so = r * ROWB1 + (cc ^ (r & 7)) * 16;
            size_t   go = (size_t)r * Kdim + k0 + cc * 8;
            CP_ASYNC(sb + so, Ah + go);
            CP_ASYNC(sb + T1_B + so, Bh + go);
        }
    };

    float acc[4][4][4];
    #pragma unroll
    for (int a = 0; a < 4; a++)
        #pragma unroll
        for (int b = 0; b < 4; b++)
            #pragma unroll
            for (int c = 0; c < 4; c++) acc[a][b][c] = 0.0f;

    const int rowA = wm * 64 + (l & 15);
    const uint32_t sA = (uint32_t)(rowA & 7);
    const uint32_t aRow = (uint32_t)rowA * ROWB1;
    const int colA0 = l >> 4;
    const int gB = l >> 3;
    const int rowB = wn * 32 + (l & 7) + (gB >> 1) * 8;
    const uint32_t sB = (uint32_t)(rowB & 7);
    const uint32_t bRow = (uint32_t)rowB * ROWB1;
    const int colB0 = gB & 1;

    load_stage(0, 0);   CP_COMMIT();
    load_stage(1, KC1); CP_COMMIT();

    for (int c = 0; c < NC; c++) {
        CP_WAIT1();
        __syncthreads();
        if (c + 2 < NC) load_stage((c + 2) % 3, (c + 2) * KC1);
        CP_COMMIT();

        uint32_t st = sbase + (c % 3) * STAGE1;
        #pragma unroll
        for (int k16 = 0; k16 < 4; k16++) {
            const uint32_t cA = (uint32_t)((colA0 + k16 * 2)) ^ sA;
            const uint32_t cB = (uint32_t)((colB0 + k16 * 2)) ^ sB;
            uint32_t aH = st + aRow + cA * 16;
            uint32_t bH = st + T1_B + bRow + cB * 16;
            uint32_t ah[4][4], bh[2][4];
            #pragma unroll
            for (int mt = 0; mt < 4; mt++) ldsm4(ah[mt], aH + mt * (16 * ROWB1));
            #pragma unroll
            for (int p = 0; p < 2; p++)    ldsm4(bh[p], bH + p * (16 * ROWB1));
            #pragma unroll
            for (int mt = 0; mt < 4; mt++)
                #pragma unroll
                for (int nt = 0; nt < 4; nt++)
                    mma16816(acc[mt][nt], ah[mt], &bh[nt >> 1][(nt & 1) * 2]);
        }
    }

    const int rb = wm * 64 + (l >> 2);
    const int cb = wn * 32 + 2 * (l & 3);
    #pragma unroll
    for (int mt = 0; mt < 4; mt++)
        #pragma unroll
        for (int i2 = 0; i2 < 2; i2++) {
            int row = mBase + rb + mt * 16 + i2 * 8;
            #pragma unroll
            for (int nt = 0; nt < 4; nt++) {
                int col = nBase + cb + nt * 8;
                size_t idx = (size_t)row * Nout + col;
                float v0 = acc[mt][nt][2 * i2], v1 = acc[mt][nt][2 * i2 + 1];
                if (EPI == 0) {
                    *(__half2*)&g_bh[idx] = __halves2half2(
                        __float2half_rn(v0), __float2half_rn(v1));
                    float u0 = RATEV * v0, u1 = RATEV * v1;
                    *(__half2*)&g_uh[idx] = __halves2half2(
                        __float2half_rn(u0), __float2half_rn(u1));
                    float a0 = fmaxf(u0 - LAMV, 0.0f), a1 = fmaxf(u1 - LAMV, 0.0f);
                    *(__half2*)&g_ahi[idx] = __halves2half2(
                        __float2half_rn(a0), __float2half_rn(a1));
                } else {
                    __half2 bh2 = *(__half2*)&g_bh[idx];
                    __half2 uh2 = *(__half2*)&g_uh[idx];
                    float b0 = __half2float(__low2half(bh2));
                    float b1 = __half2float(__high2half(bh2));
                    float u0 = __half2float(__low2half(uh2));
                    float u1 = __half2float(__high2half(uh2));
                    float d0 = g_diag[col], d1 = g_diag[col + 1];
                    float ao0 = fmaxf(u0 - LAMV, 0.0f), ao1 = fmaxf(u1 - LAMV, 0.0f);
                    float aG0 = v0 - ao0 * d0, aG1 = v1 - ao1 * d1;
                    float un0 = u0 + RATEV * (b0 - aG0 - u0);
                    float un1 = u1 + RATEV * (b1 - aG1 - u1);
                    *(__half2*)&g_uh[idx] = __halves2half2(
                        __float2half_rn(un0), __float2half_rn(un1));
                    float a0 = fmaxf(un0 - LAMV, 0.0f), a1 = fmaxf(un1 - LAMV, 0.0f);
                    *(__half2*)&g_ahi[idx] = __halves2half2(
                        __float2half_rn(a0), __float2half_rn(a1));
                }
            }
        }
}

// ========== 64x128 1-term GEMM (KC=64, 3-stage, 128thr, 3 CTAs/SM) ==========
// EPI 1 (t):   A=ahi, B=Whi -> thi fp16
// EPI 2 (out): A=ahi, B=Whi -> out fp32
template <int EPI>
__global__ __launch_bounds__(128, 3)
void lca_gemm_small(float* __restrict__ outp)
{
    constexpr int Kdim = DLCA;
    constexpr int Nout = DMODEL;
    constexpr int NC   = Kdim / KC1;

    extern __shared__ __align__(16) char smem[];
    const uint32_t sbase = smem_u32(smem);

    const int tid = threadIdx.x;
    const int wid = tid >> 5, l = tid & 31;
    const int wn = wid;
    const int mBase = blockIdx.y * 64;
    const int nBase = blockIdx.x * 128;

    const __half* Ah = g_ahi + (size_t)mBase * Kdim;
    const __half* Bh = g_Whi + (size_t)nBase * Kdim;

    auto load_stage = [&](int s, int k0) {
        uint32_t sb = sbase + s * STAGEE;
        #pragma unroll
        for (int i = 0; i < 4; i++) {
            int u = tid + i * 128;
            int r = u >> 3, cc = u & 7;
            uint32_t so = r * ROWB1 + (cc ^ (r & 7)) * 16;
            CP_ASYNC(sb + so, Ah + (size_t)r * Kdim + k0 + cc * 8);
        }
        #pragma unroll
        for (int i = 0; i < 8; i++) {
            int u = tid + i * 128;
            int r = u >> 3, cc = u & 7;
            uint32_t so = r * ROWB1 + (cc ^ (r & 7)) * 16;
            CP_ASYNC(sb + TE_A + so, Bh + (size_t)r * Kdim + k0 + cc * 8);
        }
    };

    float acc[4][4][4];
    #pragma unroll
    for (int a = 0; a < 4; a++)
        #pragma unroll
        for (int b = 0; b < 4; b++)
            #pragma unroll
            for (int c = 0; c < 4; c++) acc[a][b][c] = 0.0f;

    const int rowA = l & 15;
    const uint32_t sA = (uint32_t)(rowA & 7);
    const uint32_t aRow = (uint32_t)rowA * ROWB1;
    const int colA0 = l >> 4;
    const int gB = l >> 3;
    const int rowB = wn * 32 + (l & 7) + (gB >> 1) * 8;
    const uint32_t sB = (uint32_t)(rowB & 7);
    const uint32_t bRow = (uint32_t)rowB * ROWB1;
    const int colB0 = gB & 1;

    load_stage(0, 0);   CP_COMMIT();
    load_stage(1, KC1); CP_COMMIT();

    for (int c = 0; c < NC; c++) {
        CP_WAIT1();
        __syncthreads();
        if (c + 2 < NC) load_stage((c + 2) % 3, (c + 2) * KC1);
        CP_COMMIT();

        uint32_t st = sbase + (c % 3) * STAGEE;
        #pragma unroll
        for (int k16 = 0; k16 < 4; k16++) {
            const uint32_t cA = (uint32_t)((colA0 + k16 * 2)) ^ sA;
            const uint32_t cB = (uint32_t)((colB0 + k16 * 2)) ^ sB;
            uint32_t aH = st + aRow + cA * 16;
            uint32_t bH = st + TE_A + bRow + cB * 16;
            uint32_t ah[4][4], bh[2][4];
            #pragma unroll
            for (int mt = 0; mt < 4; mt++) ldsm4(ah[mt], aH + mt * (16 * ROWB1));
            #pragma unroll
            for (int p = 0; p < 2; p++)    ldsm4(bh[p], bH + p * (16 * ROWB1));
            #pragma unroll
            for (int mt = 0; mt < 4; mt++)
                #pragma unroll
                for (int nt = 0; nt < 4; nt++)
                    mma16816(acc[mt][nt], ah[mt], &bh[nt >> 1][(nt & 1) * 2]);
        }
    }

    const int rb = l >> 2;
    const int cb = wn * 32 + 2 * (l & 3);
    #pragma unroll
    for (int mt = 0; mt < 4; mt++)
        #pragma unroll
        for (int i2 = 0; i2 < 2; i2++) {
            int row = mBase + rb + mt * 16 + i2 * 8;
            #pragma unroll
            for (int nt = 0; nt < 4; nt++) {
                int col = nBase + cb + nt * 8;
                size_t idx = (size_t)row * Nout + col;
                if (EPI == 1) {
                    *(__half2*)&g_thi[idx] = __halves2half2(
                        __float2half_rn(acc[mt][nt][2 * i2]),
                        __float2half_rn(acc[mt][nt][2 * i2 + 1]));
                } else {
                    *(float2*)&outp[idx] = make_float2(acc[mt][nt][2 * i2],
                                                       acc[mt][nt][2 * i2 + 1]);
                }
            }
        }
}

// ---------------- launch ----------------
extern "C" void kernel_launch(void* const* d_in, const int* in_sizes, int n_in,
                              void* d_out, int out_size)
{
    const float* x = (const float*)d_in[0];
    const float* W = (const float*)d_in[1];
    if (n_in >= 2 && in_sizes[0] < in_sizes[1]) { const float* t = x; x = W; W = t; }
    float* out = (float*)d_out;

    cudaFuncSetAttribute(lca_gemm_big<0>,   cudaFuncAttributeMaxDynamicSharedMemorySize, SMEM1);
    cudaFuncSetAttribute(lca_gemm_big<3>,   cudaFuncAttributeMaxDynamicSharedMemorySize, SMEM1);
    cudaFuncSetAttribute(lca_gemm_small<1>, cudaFuncAttributeMaxDynamicSharedMemorySize, SMEME);
    cudaFuncSetAttribute(lca_gemm_small<2>, cudaFuncAttributeMaxDynamicSharedMemorySize, SMEME);

    split_x_kernel<<<(MDIM * DMODEL) / 256, 256>>>(x);
    splitW_kernel<<<dim3(DLCA / 32, DMODEL / 32), dim3(32, 8)>>>(W);
    diag_kernel<<<DLCA / 256, 256>>>(W);

    dim3 gridB(DLCA / 128, MDIM / 128);     // (32, 64)  = 2048 CTAs
    dim3 gridS(DMODEL / 128, MDIM / 64);    // (8, 128)  = 1024 CTAs

    lca_gemm_big<0><<<gridB, 256, SMEM1>>>();                 // b-init
    for (int s = 0; s < 9; s++) {
        lca_gemm_small<1><<<gridS, 128, SMEME>>>(nullptr);    // t = a @ W~^T
        lca_gemm_big<3><<<gridB, 256, SMEM1>>>();             // u update
    }
    lca_gemm_small<2><<<gridS, 128, SMEME>>>(out);            // out
}